// round 10
// baseline (speedup 1.0000x reference)
#include <cuda_runtime.h>
#include <cstdint>

// 2D acoustic FDTD, 500 steps, 8 shots, 256x256, 128 recs/shot.
// One persistent kernel; shot = 8-CTA cluster; field in SMEM + registers.
// TEMPORAL BLOCKING: 2 steps per cluster.sync via ghost-row recompute.
// 4-buffer rotation makes each double-step race-free with one trailing sync.
// Packed f32x2 (FFMA2) stencil; owner-local receivers.

#define DT 0.001f
#define DX 10.0f

constexpr int NT   = 500;
constexpr int NS   = 8;
constexpr int NZ   = 256;
constexpr int NXC  = 256;
constexpr int NREC = 128;

constexpr int CSZ  = 8;
constexpr int ROWS = NZ / CSZ;          // 32
constexpr int NTHREADS = 1024;
constexpr int COL4 = NXC / 4;           // 64
constexpr int RG   = NTHREADS / COL4;   // 16
constexpr int RPT  = ROWS / RG;         // 2

constexpr int BUF_ELEMS = ROWS * NXC;       // 8192
constexpr int BUF_BYTES = BUF_ELEMS * 4;    // 32768
constexpr uint32_t PAR_DELTA = 2u * BUF_BYTES;  // parity-1 neighbor addr shift
constexpr size_t SMEM_BYTES = (size_t)(4 * BUF_ELEMS + 512) * sizeof(float);

typedef unsigned long long u64;

// ---------------------------------------------------------------- PTX helpers
__device__ __forceinline__ uint32_t cvta_smem(const void* p) {
    return (uint32_t)__cvta_generic_to_shared(p);
}
__device__ __forceinline__ uint32_t mapa_cluster(uint32_t laddr, uint32_t rank) {
    uint32_t r;
    asm("mapa.shared::cluster.u32 %0, %1, %2;" : "=r"(r) : "r"(laddr), "r"(rank));
    return r;
}
__device__ __forceinline__ float4 ld_dsmem_v4(uint32_t addr) {
    float4 v;
    asm volatile("ld.shared::cluster.v4.f32 {%0,%1,%2,%3}, [%4];"
                 : "=f"(v.x), "=f"(v.y), "=f"(v.z), "=f"(v.w) : "r"(addr));
    return v;
}
__device__ __forceinline__ float ld_dsmem_f32(uint32_t addr) {
    float v;
    asm volatile("ld.shared::cluster.f32 %0, [%1];" : "=f"(v) : "r"(addr));
    return v;
}
__device__ __forceinline__ void cluster_sync_() {
    asm volatile("barrier.cluster.arrive.aligned;" ::: "memory");
    asm volatile("barrier.cluster.wait.aligned;" ::: "memory");
}
__device__ __forceinline__ uint32_t cluster_rank_() {
    uint32_t r;
    asm("mov.u32 %0, %%cluster_ctarank;" : "=r"(r));
    return r;
}

// ---- packed f32x2 ops -------------------------------------------------------
__device__ __forceinline__ u64 pk(float a, float b) {
    u64 r; asm("mov.b64 %0, {%1, %2};" : "=l"(r) : "f"(a), "f"(b)); return r;
}
__device__ __forceinline__ float2 upk(u64 v) {
    float2 f; asm("mov.b64 {%0, %1}, %2;" : "=f"(f.x), "=f"(f.y) : "l"(v)); return f;
}
__device__ __forceinline__ u64 addx2(u64 a, u64 b) {
    u64 r; asm("add.rn.f32x2 %0, %1, %2;" : "=l"(r) : "l"(a), "l"(b)); return r;
}
__device__ __forceinline__ u64 mulx2(u64 a, u64 b) {
    u64 r; asm("mul.rn.f32x2 %0, %1, %2;" : "=l"(r) : "l"(a), "l"(b)); return r;
}
__device__ __forceinline__ u64 fmax2(u64 a, u64 b, u64 c) {
    u64 r; asm("fma.rn.f32x2 %0, %1, %2, %3;" : "=l"(r) : "l"(a), "l"(b), "l"(c)); return r;
}

// one FDTD point-update for 4 columns, packed math.
// np01/np23 hold NEGATED prev.
__device__ __forceinline__ float4 fdtd4(const float4 cc, const float4 vN, const float4 vS,
                                        float lft, float rgt,
                                        u64 np01, u64 np23, u64 k01, u64 k23) {
    const u64 TWO2 = pk(2.f, 2.f);
    const u64 NEG4 = pk(-4.f, -4.f);
    const u64 c01 = pk(cc.x, cc.y), c23 = pk(cc.z, cc.w);
    const u64 n01 = pk(vN.x, vN.y), n23 = pk(vN.z, vN.w);
    const u64 s01 = pk(vS.x, vS.y), s23 = pk(vS.z, vS.w);
    const u64 L0 = pk(lft,  cc.x);
    const u64 M  = pk(cc.y, cc.z);
    const u64 R1 = pk(cc.w, rgt);
    u64 lap01 = addx2(addx2(n01, s01), addx2(L0, M));
    u64 lap23 = addx2(addx2(n23, s23), addx2(M, R1));
    lap01 = fmax2(c01, NEG4, lap01);
    lap23 = fmax2(c23, NEG4, lap23);
    const u64 nv01 = fmax2(k01, lap01, fmax2(c01, TWO2, np01));
    const u64 nv23 = fmax2(k23, lap23, fmax2(c23, TWO2, np23));
    const float2 a = upk(nv01), b = upk(nv23);
    return make_float4(a.x, a.y, b.x, b.y);
}

// ---------------------------------------------------------------- kernel
__global__ void __cluster_dims__(CSZ, 1, 1) __launch_bounds__(NTHREADS, 1)
wave_kernel(const float* __restrict__ x,     // (NT, NS)
            const float* __restrict__ vp,    // (NZ, NXC)
            const int*   __restrict__ src,   // (NS, 2)
            const int*   __restrict__ rec,   // (NS, NREC, 2)
            float*       __restrict__ out)   // (NT, NS, NREC)
{
    extern __shared__ float sm[];
    float* buf0 = sm;
    float* buf1 = sm + BUF_ELEMS;
    float* buf2 = sm + 2 * BUF_ELEMS;
    float* buf3 = sm + 3 * BUF_ELEMS;
    float* xs   = sm + 4 * BUF_ELEMS;

    __shared__ int rcnt;
    __shared__ int2 rlist[NREC];

    const int tid  = threadIdx.x;
    const uint32_t rank = cluster_rank_();
    const int shot = blockIdx.x / CSZ;

    const int col4 = tid & (COL4 - 1);
    const int rg   = tid >> 6;           // 0..15
    const int lr0  = rg * RPT;
    const int xcol = col4 * 4;
    const bool has_n = (rank > 0);
    const bool has_s = (rank < CSZ - 1);
    const bool gh_n = (rg == 0 && has_n);        // computes north ghost row
    const bool gh_s = (rg == RG - 1 && has_s);   // computes south ghost row

    // --- init ----------------------------------------------------------------
    for (int i = tid; i < 4 * BUF_ELEMS; i += NTHREADS) sm[i] = 0.f;
    for (int i = tid; i < NT; i += NTHREADS) xs[i] = x[i * NS + shot];
    if (tid == 0) rcnt = 0;
    __syncthreads();

    // claim receivers owned by this CTA
    if (tid < NREC) {
        const int gi = shot * NREC + tid;
        const int rz = rec[gi * 2 + 0];
        const int rx = rec[gi * 2 + 1];
        if ((uint32_t)(rz >> 5) == rank) {
            int s = atomicAdd(&rcnt, 1);
            rlist[s] = make_int2((rz & 31) * NXC + rx, shot * NREC + tid);
        }
    }

    // c2 in packed registers (own rows + ghost row)
    u64 k01[RPT], k23[RPT], kg01 = 0, kg23 = 0;
    const float sc = DT / DX;
#pragma unroll
    for (int j = 0; j < RPT; j++) {
        const int g = (int)rank * ROWS + lr0 + j;
        float4 v = *(const float4*)(vp + g * NXC + xcol);
        float a = v.x * sc, b = v.y * sc, c = v.z * sc, d = v.w * sc;
        k01[j] = pk(a * a, b * b);
        k23[j] = pk(c * c, d * d);
    }
    if (gh_n || gh_s) {
        const int gz = gh_n ? (int)rank * ROWS - 1 : (int)rank * ROWS + ROWS;
        float4 v = *(const float4*)(vp + gz * NXC + xcol);
        float a = v.x * sc, b = v.y * sc, c = v.z * sc, d = v.w * sc;
        kg01 = pk(a * a, b * b);
        kg23 = pk(c * c, d * d);
    }

    const u64 NEG1 = pk(-1.f, -1.f);

    // field registers: cur (float4, time t) and negated prev (packed)
    float4 cC[RPT];
    u64 np01[RPT], np23[RPT];
#pragma unroll
    for (int j = 0; j < RPT; j++) {
        cC[j] = make_float4(0.f, 0.f, 0.f, 0.f);
        np01[j] = pk(0.f, 0.f);
        np23[j] = pk(0.f, 0.f);
    }

    // source ownership (own rows + ghost rows)
    const int sz = src[shot * 2 + 0];
    const int sx = src[shot * 2 + 1];
    const int sj = sz - ((int)rank * ROWS + lr0);
    const bool sin_x = (sx >= xcol && sx < xcol + 4);
    const bool shere = (sj >= 0 && sj < RPT && sin_x);
    const bool sghn = gh_n && (sz == (int)rank * ROWS - 1) && sin_x;
    const bool sghs = gh_s && (sz == (int)rank * ROWS + ROWS) && sin_x;
    const int scomp = sx - xcol;

    // neighbor smem base addresses (offsets added per use; parity via +PAR_DELTA)
    uint32_t nbase = 0, sbase = 0;
    if (gh_n) nbase = mapa_cluster(cvta_smem(sm), rank - 1);
    if (gh_s) sbase = mapa_cluster(cvta_smem(sm), rank + 1);

    // neighbor byte offsets, parity 0 (prev = buf0, cur = buf1)
    // north ghost: its rows 30 (N of ghost), 31 (ghost center); prev row 31
    const uint32_t o_nc30 = (uint32_t)BUF_BYTES + (uint32_t)((ROWS - 2) * NXC + xcol) * 4u;
    const uint32_t o_nc31 = (uint32_t)BUF_BYTES + (uint32_t)((ROWS - 1) * NXC + xcol) * 4u;
    const uint32_t o_np31 = (uint32_t)((ROWS - 1) * NXC + xcol) * 4u;
    // south ghost: its rows 0 (ghost center), 1 (S of ghost); prev row 0
    const uint32_t o_sc0 = (uint32_t)BUF_BYTES + (uint32_t)(xcol) * 4u;
    const uint32_t o_sc1 = (uint32_t)BUF_BYTES + (uint32_t)(NXC + xcol) * 4u;
    const uint32_t o_sp0 = (uint32_t)(xcol) * 4u;

    __syncthreads();
    const bool samp = (tid < rcnt);
    int roff = 0;
    float* outp = out;
    if (samp) {
        int2 e = rlist[tid];
        roff = e.x;
        outp = out + e.y;
    }

    cluster_sync_();  // zeroed buffers visible cluster-wide

    // --- one substep over own rows -------------------------------------------
    // vNb used by rg0 as row-above; vSb used by rg15 as row-below.
    auto sub = [&](const float* __restrict__ cur, float* __restrict__ nxt,
                   float amp, float4 vNb, float4 vSb) {
        float4 vN = (rg == 0) ? vNb
                  : *(const float4*)(cur + (lr0 - 1) * NXC + xcol);
#pragma unroll
        for (int j = 0; j < RPT; j++) {
            const int lr = lr0 + j;
            const float4 cc = cC[j];
            float4 vS;
            if (j < RPT - 1)            vS = cC[j + 1];
            else if (rg == RG - 1)      vS = vSb;
            else                        vS = *(const float4*)(cur + (lr + 1) * NXC + xcol);

            const float lft = (xcol > 0)       ? cur[lr * NXC + xcol - 1] : 0.f;
            const float rgt = (xcol + 4 < NXC) ? cur[lr * NXC + xcol + 4] : 0.f;

            float4 nv = fdtd4(cc, vN, vS, lft, rgt, np01[j], np23[j], k01[j], k23[j]);

            if (shere && j == sj) {
                if      (scomp == 0) nv.x += amp;
                else if (scomp == 1) nv.y += amp;
                else if (scomp == 2) nv.z += amp;
                else                 nv.w += amp;
            }

            *(float4*)(nxt + lr * NXC + xcol) = nv;
            np01[j] = mulx2(pk(cc.x, cc.y), NEG1);
            np23[j] = mulx2(pk(cc.z, cc.w), NEG1);
            cC[j] = nv;
            vN = cc;
        }
    };

    // --- one double step (2 time steps, ONE cluster sync) --------------------
    auto dstep = [&](float* __restrict__ n1, float* __restrict__ n2,
                     uint32_t ad, int t) {
        const int to1 = (t + 2 < NT - 1) ? t + 2 : NT - 1;
        const float amp1 = xs[t] + xs[to1];

        // ghost rows at t+1 (boundary threads only); also capture halo vN/vS at t
        float4 gN = make_float4(0.f, 0.f, 0.f, 0.f);
        float4 gS = make_float4(0.f, 0.f, 0.f, 0.f);
        float4 vNb = make_float4(0.f, 0.f, 0.f, 0.f);
        float4 vSb = make_float4(0.f, 0.f, 0.f, 0.f);
        if (gh_n) {
            const float4 g30 = ld_dsmem_v4(nbase + o_nc30 + ad);
            const float4 g31 = ld_dsmem_v4(nbase + o_nc31 + ad);
            const float4 gp  = ld_dsmem_v4(nbase + o_np31 + ad);
            const float gl = (xcol > 0)       ? ld_dsmem_f32(nbase + o_nc31 + ad - 4u)  : 0.f;
            const float gr = (xcol + 4 < NXC) ? ld_dsmem_f32(nbase + o_nc31 + ad + 16u) : 0.f;
            gN = fdtd4(g31, g30, cC[0], gl, gr,
                       mulx2(pk(gp.x, gp.y), NEG1), mulx2(pk(gp.z, gp.w), NEG1),
                       kg01, kg23);
            if (sghn) {
                if      (scomp == 0) gN.x += amp1;
                else if (scomp == 1) gN.y += amp1;
                else if (scomp == 2) gN.z += amp1;
                else                 gN.w += amp1;
            }
            vNb = g31;
        }
        if (gh_s) {
            const float4 g0 = ld_dsmem_v4(sbase + o_sc0 + ad);
            const float4 g1 = ld_dsmem_v4(sbase + o_sc1 + ad);
            const float4 gp = ld_dsmem_v4(sbase + o_sp0 + ad);
            const float gl = (xcol > 0)       ? ld_dsmem_f32(sbase + o_sc0 + ad - 4u)  : 0.f;
            const float gr = (xcol + 4 < NXC) ? ld_dsmem_f32(sbase + o_sc0 + ad + 16u) : 0.f;
            gS = fdtd4(g0, cC[RPT - 1], g1, gl, gr,
                       mulx2(pk(gp.x, gp.y), NEG1), mulx2(pk(gp.z, gp.w), NEG1),
                       kg01, kg23);
            if (sghs) {
                if      (scomp == 0) gS.x += amp1;
                else if (scomp == 1) gS.y += amp1;
                else if (scomp == 2) gS.z += amp1;
                else                 gS.w += amp1;
            }
            vSb = g0;
        }

        // substep 1: t -> t+1 into n1 (cur = the buffer cC mirrors; reads only
        // interior rows of it, which match cC/SMEM from last double-step)
        sub(n1 - 0 + 0 == nullptr ? n1 : /*cur*/ nullptr, n1, amp1, vNb, vSb);
        (void)0;
    };

    // NOTE: dstep above needs 'cur'; restructure: implement double steps inline.

    for (int t4 = 0; t4 < NT; t4 += 4) {
#pragma unroll
        for (int half = 0; half < 2; half++) {
            const int t = t4 + 2 * half;
            const uint32_t ad = half ? PAR_DELTA : 0u;
            const float* cur = half ? buf3 : buf1;
            float* n1 = half ? buf0 : buf2;
            float* n2 = half ? buf1 : buf3;

            const int to1 = (t + 2 < NT - 1) ? t + 2 : NT - 1;
            const float amp1 = xs[t] + xs[to1];

            float4 gN = make_float4(0.f, 0.f, 0.f, 0.f);
            float4 gS = make_float4(0.f, 0.f, 0.f, 0.f);
            float4 vNb = make_float4(0.f, 0.f, 0.f, 0.f);
            float4 vSb = make_float4(0.f, 0.f, 0.f, 0.f);
            if (gh_n) {
                const float4 g30 = ld_dsmem_v4(nbase + o_nc30 + ad);
                const float4 g31 = ld_dsmem_v4(nbase + o_nc31 + ad);
                const float4 gp  = ld_dsmem_v4(nbase + o_np31 + ad);
                const float gl = (xcol > 0)       ? ld_dsmem_f32(nbase + o_nc31 + ad - 4u)  : 0.f;
                const float gr = (xcol + 4 < NXC) ? ld_dsmem_f32(nbase + o_nc31 + ad + 16u) : 0.f;
                gN = fdtd4(g31, g30, cC[0], gl, gr,
                           mulx2(pk(gp.x, gp.y), NEG1), mulx2(pk(gp.z, gp.w), NEG1),
                           kg01, kg23);
                if (sghn) {
                    if      (scomp == 0) gN.x += amp1;
                    else if (scomp == 1) gN.y += amp1;
                    else if (scomp == 2) gN.z += amp1;
                    else                 gN.w += amp1;
                }
                vNb = g31;
            }
            if (gh_s) {
                const float4 g0 = ld_dsmem_v4(sbase + o_sc0 + ad);
                const float4 g1 = ld_dsmem_v4(sbase + o_sc1 + ad);
                const float4 gp = ld_dsmem_v4(sbase + o_sp0 + ad);
                const float gl = (xcol > 0)       ? ld_dsmem_f32(sbase + o_sc0 + ad - 4u)  : 0.f;
                const float gr = (xcol + 4 < NXC) ? ld_dsmem_f32(sbase + o_sc0 + ad + 16u) : 0.f;
                gS = fdtd4(g0, cC[RPT - 1], g1, gl, gr,
                           mulx2(pk(gp.x, gp.y), NEG1), mulx2(pk(gp.z, gp.w), NEG1),
                           kg01, kg23);
                if (sghs) {
                    if      (scomp == 0) gS.x += amp1;
                    else if (scomp == 1) gS.y += amp1;
                    else if (scomp == 2) gS.z += amp1;
                    else                 gS.w += amp1;
                }
                vSb = g0;
            }

            // substep 1: t -> t+1 into n1
            sub(cur, n1, amp1, vNb, vSb);

            __syncthreads();          // n1 visible CTA-wide
            if (samp) {
                *outp = n1[roff];
                outp += NS * NREC;
            }

            // substep 2: t+1 -> t+2 into n2 (no cross-CTA data: ghosts in regs)
            const int to2 = (t + 3 < NT - 1) ? t + 3 : NT - 1;
            const float amp2 = xs[t + 1] + xs[to2];
            sub(n1, n2, amp2, gN, gS);

            __syncthreads();          // n2 visible CTA-wide
            if (samp) {
                *outp = n2[roff];
                outp += NS * NREC;
            }

            cluster_sync_();          // ONE cluster barrier per 2 steps
        }
    }
}

// ---------------------------------------------------------------- launch
extern "C" void kernel_launch(void* const* d_in, const int* in_sizes, int n_in,
                              void* d_out, int out_size)
{
    const float* x   = (const float*)d_in[0];
    const float* vp  = (const float*)d_in[1];
    const int*   src = (const int*)d_in[2];
    const int*   rec = (const int*)d_in[3];
    float*       out = (float*)d_out;

    cudaFuncSetAttribute((const void*)wave_kernel,
                         cudaFuncAttributeMaxDynamicSharedMemorySize,
                         (int)SMEM_BYTES);

    wave_kernel<<<NS * CSZ, NTHREADS, SMEM_BYTES>>>(x, vp, src, rec, out);
}

// round 11
// speedup vs baseline: 1.0572x; 1.0572x over previous
#include <cuda_runtime.h>
#include <cstdint>

// 2D acoustic FDTD, 500 steps, 8 shots, 256x256, 128 recs/shot.
// One persistent kernel; shot = 8-CTA cluster; field in SMEM + registers.
// Packed f32x2 (FFMA2) stencil (R8 body). Per-step sync = custom all-to-all
// mbarrier cluster barrier (full barrier -> parity-safe; HW-sleep waits).

#define DT 0.001f
#define DX 10.0f

constexpr int NT   = 500;
constexpr int NS   = 8;
constexpr int NZ   = 256;
constexpr int NXC  = 256;
constexpr int NREC = 128;

constexpr int CSZ  = 8;
constexpr int ROWS = NZ / CSZ;          // 32
constexpr int NTHREADS = 1024;
constexpr int COL4 = NXC / 4;           // 64
constexpr int RG   = NTHREADS / COL4;   // 16
constexpr int RPT  = ROWS / RG;         // 2

constexpr int BUF_ELEMS = ROWS * NXC;   // 8192
constexpr size_t SMEM_BYTES = (size_t)(2 * BUF_ELEMS + 512) * sizeof(float);

typedef unsigned long long u64;

// ---------------------------------------------------------------- PTX helpers
__device__ __forceinline__ uint32_t cvta_smem(const void* p) {
    return (uint32_t)__cvta_generic_to_shared(p);
}
__device__ __forceinline__ uint32_t mapa_cluster(uint32_t laddr, uint32_t rank) {
    uint32_t r;
    asm("mapa.shared::cluster.u32 %0, %1, %2;" : "=r"(r) : "r"(laddr), "r"(rank));
    return r;
}
__device__ __forceinline__ float4 ld_dsmem_v4(uint32_t addr) {
    float4 v;
    asm volatile("ld.shared::cluster.v4.f32 {%0,%1,%2,%3}, [%4];"
                 : "=f"(v.x), "=f"(v.y), "=f"(v.z), "=f"(v.w) : "r"(addr));
    return v;
}
__device__ __forceinline__ void cluster_sync_() {
    asm volatile("barrier.cluster.arrive.aligned;" ::: "memory");
    asm volatile("barrier.cluster.wait.aligned;" ::: "memory");
}
__device__ __forceinline__ uint32_t cluster_rank_() {
    uint32_t r;
    asm("mov.u32 %0, %%cluster_ctarank;" : "=r"(r));
    return r;
}
__device__ __forceinline__ void mbar_init(uint32_t addr, uint32_t count) {
    asm volatile("mbarrier.init.shared.b64 [%0], %1;" :: "r"(addr), "r"(count) : "memory");
}
__device__ __forceinline__ void mbar_arrive_remote(uint32_t addr) {
    asm volatile("mbarrier.arrive.release.cluster.shared::cluster.b64 _, [%0];"
                 :: "r"(addr) : "memory");
}
__device__ __forceinline__ void mbar_wait(uint32_t addr, uint32_t parity) {
    asm volatile(
        "{\n\t"
        ".reg .pred P;\n\t"
        "WL%=:\n\t"
        "mbarrier.try_wait.parity.acquire.cluster.shared::cta.b64 P, [%0], %1, 0x989680;\n\t"
        "@!P bra WL%=;\n\t"
        "}"
        :: "r"(addr), "r"(parity) : "memory");
}

// ---- packed f32x2 ops -------------------------------------------------------
__device__ __forceinline__ u64 pk(float a, float b) {
    u64 r; asm("mov.b64 %0, {%1, %2};" : "=l"(r) : "f"(a), "f"(b)); return r;
}
__device__ __forceinline__ float2 upk(u64 v) {
    float2 f; asm("mov.b64 {%0, %1}, %2;" : "=f"(f.x), "=f"(f.y) : "l"(v)); return f;
}
__device__ __forceinline__ u64 addx2(u64 a, u64 b) {
    u64 r; asm("add.rn.f32x2 %0, %1, %2;" : "=l"(r) : "l"(a), "l"(b)); return r;
}
__device__ __forceinline__ u64 mulx2(u64 a, u64 b) {
    u64 r; asm("mul.rn.f32x2 %0, %1, %2;" : "=l"(r) : "l"(a), "l"(b)); return r;
}
__device__ __forceinline__ u64 fmax2(u64 a, u64 b, u64 c) {
    u64 r; asm("fma.rn.f32x2 %0, %1, %2, %3;" : "=l"(r) : "l"(a), "l"(b), "l"(c)); return r;
}

// ---------------------------------------------------------------- kernel
__global__ void __cluster_dims__(CSZ, 1, 1) __launch_bounds__(NTHREADS, 1)
wave_kernel(const float* __restrict__ x,     // (NT, NS)
            const float* __restrict__ vp,    // (NZ, NXC)
            const int*   __restrict__ src,   // (NS, 2)
            const int*   __restrict__ rec,   // (NS, NREC, 2)
            float*       __restrict__ out)   // (NT, NS, NREC)
{
    extern __shared__ float sm[];
    float* buf0 = sm;
    float* buf1 = sm + BUF_ELEMS;
    float* xs   = sm + 2 * BUF_ELEMS;

    __shared__ uint64_t cbar;              // cluster barrier (count = CSZ)
    __shared__ int rcnt;
    __shared__ int2 rlist[NREC];

    const int tid  = threadIdx.x;
    const uint32_t rank = cluster_rank_();
    const int shot = blockIdx.x / CSZ;

    const int col4 = tid & (COL4 - 1);
    const int rg   = tid >> 6;           // 0..15
    const int lr0  = rg * RPT;
    const int xcol = col4 * 4;
    const bool has_n = (rank > 0);
    const bool has_s = (rank < CSZ - 1);

    // --- init ----------------------------------------------------------------
    for (int i = tid; i < BUF_ELEMS; i += NTHREADS) { buf0[i] = 0.f; buf1[i] = 0.f; }
    for (int i = tid; i < NT; i += NTHREADS) xs[i] = x[i * NS + shot];
    if (tid == 0) {
        rcnt = 0;
        mbar_init(cvta_smem(&cbar), CSZ);   // 8 arrives per phase (one per CTA)
    }
    __syncthreads();

    // claim receivers owned by this CTA
    if (tid < NREC) {
        const int gi = shot * NREC + tid;
        const int rz = rec[gi * 2 + 0];
        const int rx = rec[gi * 2 + 1];
        if ((uint32_t)(rz >> 5) == rank) {
            int s = atomicAdd(&rcnt, 1);
            rlist[s] = make_int2((rz & 31) * NXC + rx, shot * NREC + tid);
        }
    }

    // c2 in packed registers
    u64 k01[RPT], k23[RPT];
    const float sc = DT / DX;
#pragma unroll
    for (int j = 0; j < RPT; j++) {
        const int g = (int)rank * ROWS + lr0 + j;
        float4 v = *(const float4*)(vp + g * NXC + xcol);
        float a = v.x * sc, b = v.y * sc, c = v.z * sc, d = v.w * sc;
        k01[j] = pk(a * a, b * b);
        k23[j] = pk(c * c, d * d);
    }

    const u64 TWO2 = pk(2.f, 2.f);
    const u64 NEG4 = pk(-4.f, -4.f);
    const u64 NEG1 = pk(-1.f, -1.f);

    // field registers: cur (float4) and negated prev (packed); zero at t=0
    float4 cC[RPT];
    u64 np01[RPT], np23[RPT];
#pragma unroll
    for (int j = 0; j < RPT; j++) {
        cC[j] = make_float4(0.f, 0.f, 0.f, 0.f);
        np01[j] = pk(0.f, 0.f);
        np23[j] = pk(0.f, 0.f);
    }

    // source ownership
    const int sz = src[shot * 2 + 0];
    const int sx = src[shot * 2 + 1];
    const int sj = sz - ((int)rank * ROWS + lr0);
    const bool shere = (sj >= 0 && sj < RPT && sx >= xcol && sx < xcol + 4);
    const int scomp = sx - xcol;

    // DSMEM halo addresses (both parities)
    const uint32_t sa0 = cvta_smem(buf0);
    const uint32_t sa1 = cvta_smem(buf1);
    uint32_t nh0 = 0, nh1 = 0, sh0 = 0, sh1 = 0;
    if (rg == 0 && has_n) {
        const uint32_t off = (uint32_t)((ROWS - 1) * NXC + xcol) * 4u;
        nh0 = mapa_cluster(sa0 + off, rank - 1);
        nh1 = mapa_cluster(sa1 + off, rank - 1);
    }
    if (rg == RG - 1 && has_s) {
        const uint32_t off = (uint32_t)(xcol) * 4u;
        sh0 = mapa_cluster(sa0 + off, rank + 1);
        sh1 = mapa_cluster(sa1 + off, rank + 1);
    }

    // each thread tid<CSZ owns one remote arrive target (CTA tid's barrier)
    uint32_t arr_addr = 0;
    if (tid < CSZ) arr_addr = mapa_cluster(cvta_smem(&cbar), (uint32_t)tid);
    const uint32_t my_bar = cvta_smem(&cbar);

    __syncthreads();
    const bool samp = (tid < rcnt);
    int roff = 0;
    float* outp = out;
    if (samp) {
        int2 e = rlist[tid];
        roff = e.x;
        outp = out + e.y;
    }

    cluster_sync_();  // zeroed buffers + initialized mbarriers visible

    // --- one FDTD step -------------------------------------------------------
    auto step = [&](const float* __restrict__ cur, float* __restrict__ nxt,
                    uint32_t nh, uint32_t sh, int t) {
        const int toff = (t + 2 < NT - 1) ? t + 2 : NT - 1;
        const float amp = xs[t] + xs[toff];

        // row above the strip (time-t values)
        float4 vN;
        if (rg == 0) {
            vN = has_n ? ld_dsmem_v4(nh) : make_float4(0.f, 0.f, 0.f, 0.f);
        } else {
            vN = *(const float4*)(cur + (lr0 - 1) * NXC + xcol);
        }
        u64 n01 = pk(vN.x, vN.y), n23 = pk(vN.z, vN.w);

#pragma unroll
        for (int j = 0; j < RPT; j++) {
            const int lr = lr0 + j;
            const float4 cc = cC[j];
            const u64 c01 = pk(cc.x, cc.y), c23 = pk(cc.z, cc.w);

            float4 vS;
            if (j < RPT - 1) {
                vS = cC[j + 1];
            } else if (rg == RG - 1) {
                vS = has_s ? ld_dsmem_v4(sh) : make_float4(0.f, 0.f, 0.f, 0.f);
            } else {
                vS = *(const float4*)(cur + (lr + 1) * NXC + xcol);
            }
            const u64 s01 = pk(vS.x, vS.y), s23 = pk(vS.z, vS.w);

            const float lft = (xcol > 0)       ? cur[lr * NXC + xcol - 1] : 0.f;
            const float rgt = (xcol + 4 < NXC) ? cur[lr * NXC + xcol + 4] : 0.f;

            const u64 L0 = pk(lft,  cc.x);
            const u64 M  = pk(cc.y, cc.z);
            const u64 R1 = pk(cc.w, rgt);

            u64 lap01 = addx2(addx2(n01, s01), addx2(L0, M));
            u64 lap23 = addx2(addx2(n23, s23), addx2(M, R1));
            lap01 = fmax2(c01, NEG4, lap01);
            lap23 = fmax2(c23, NEG4, lap23);

            const u64 nv01 = fmax2(k01[j], lap01, fmax2(c01, TWO2, np01[j]));
            const u64 nv23 = fmax2(k23[j], lap23, fmax2(c23, TWO2, np23[j]));

            np01[j] = mulx2(c01, NEG1);
            np23[j] = mulx2(c23, NEG1);

            const float2 a = upk(nv01), b = upk(nv23);
            float4 nv = make_float4(a.x, a.y, b.x, b.y);

            if (shere && j == sj) {
                if      (scomp == 0) nv.x += amp;
                else if (scomp == 1) nv.y += amp;
                else if (scomp == 2) nv.z += amp;
                else                 nv.w += amp;
            }

            *(float4*)(nxt + lr * NXC + xcol) = nv;
            cC[j] = nv;
            n01 = c01; n23 = c23;
        }

        // ---- custom cluster barrier (full barrier => parity-safe) ----------
        __syncthreads();                       // all CTA stores committed
        if (tid < CSZ) mbar_arrive_remote(arr_addr);   // 8 parallel arrives

        // overlap: sample own-SMEM receivers while arrives propagate
        if (samp) {
            *outp = nxt[roff];
            outp += NS * NREC;
        }

        mbar_wait(my_bar, (uint32_t)(t & 1));  // all warps; HW-sleep wait
    };

    // --- main time loop, unrolled x2 for compile-time buffer parity ----------
    for (int t2 = 0; t2 < NT; t2 += 2) {
        step(buf0, buf1, nh0, sh0, t2);
        step(buf1, buf0, nh1, sh1, t2 + 1);
    }

    cluster_sync_();  // keep cluster smem alive until all CTAs fully done
}

// ---------------------------------------------------------------- launch
extern "C" void kernel_launch(void* const* d_in, const int* in_sizes, int n_in,
                              void* d_out, int out_size)
{
    const float* x   = (const float*)d_in[0];
    const float* vp  = (const float*)d_in[1];
    const int*   src = (const int*)d_in[2];
    const int*   rec = (const int*)d_in[3];
    float*       out = (float*)d_out;

    cudaFuncSetAttribute((const void*)wave_kernel,
                         cudaFuncAttributeMaxDynamicSharedMemorySize,
                         (int)SMEM_BYTES);

    wave_kernel<<<NS * CSZ, NTHREADS, SMEM_BYTES>>>(x, vp, src, rec, out);
}